// round 3
// baseline (speedup 1.0000x reference)
#include <cuda_runtime.h>
#include <math.h>

#define D 64
#define DTXT 384
typedef unsigned long long ull;

#define MAXE  (8 * 1024 * 1024)
#define MAXNT 262144

// Scratch (static __device__ per harness rules)
__device__ ull   g_edges[MAXE];           // packed (val<<32 | col_byte_offset), row-sorted
__device__ float g_bufA[MAXNT * D];
__device__ float g_bufB[MAXNT * D];
__device__ int   g_rowptr[MAXNT + 1];
__device__ int   g_cursor[MAXNT];

__device__ __forceinline__ ull fma2(ull a, ull b, ull c) {
    ull d;
    asm("fma.rn.f32x2 %0, %1, %2, %3;" : "=l"(d) : "l"(a), "l"(b), "l"(c));
    return d;
}

// -------------------- concat emb_m | emb_a -> dst --------------------
__global__ void k_copy2(const float4* __restrict__ ma, const float4* __restrict__ aa,
                        float4* __restrict__ dst, int nm4, int ntot4) {
    int i = blockIdx.x * blockDim.x + threadIdx.x;
    if (i < ntot4) dst[i] = (i < nm4) ? __ldg(ma + i) : __ldg(aa + (i - nm4));
}

// -------------------- histogram over combined rows --------------------
__global__ void k_hist2(const int* __restrict__ mr, const int* __restrict__ ar,
                        int* __restrict__ cnt, int Em, int Et, int nm) {
    int e = blockIdx.x * blockDim.x + threadIdx.x;
    if (e < Et) {
        int r = (e < Em) ? __ldg(mr + e) : (__ldg(ar + e - Em) + nm);
        atomicAdd(&cnt[r], 1);
    }
}

// -------------------- single-block exclusive scan --------------------
__global__ void k_scan(const int* __restrict__ cnt, int* __restrict__ rowptr,
                       int* __restrict__ cursor, int N) {
    __shared__ int sp[1024];
    int tid = threadIdx.x;
    int chunk = (N + 1023) >> 10;
    int s = tid * chunk;
    int e = min(s + chunk, N);
    int sum = 0;
    for (int i = s; i < e; i++) sum += cnt[i];
    sp[tid] = sum;
    __syncthreads();
    for (int off = 1; off < 1024; off <<= 1) {
        int v = (tid >= off) ? sp[tid - off] : 0;
        __syncthreads();
        sp[tid] += v;
        __syncthreads();
    }
    int excl = (tid == 0) ? 0 : sp[tid - 1];
    for (int i = s; i < e; i++) {
        int c = cnt[i];
        rowptr[i] = excl;
        cursor[i] = excl;
        excl += c;
    }
    if (tid == 0) rowptr[N] = sp[1023];
}

// -------------------- scatter both graphs' edges into row-sorted order --------------------
__global__ void k_scatter2(const int* __restrict__ mr, const int* __restrict__ mc,
                           const float* __restrict__ mv,
                           const int* __restrict__ ar, const int* __restrict__ ac,
                           const float* __restrict__ av,
                           int* __restrict__ cursor, ull* __restrict__ edges,
                           int Em, int Et, int nm) {
    int e = blockIdx.x * blockDim.x + threadIdx.x;
    if (e >= Et) return;
    int r, c; float v;
    if (e < Em) { r = __ldg(mr + e);          c = __ldg(mc + e);          v = __ldg(mv + e); }
    else { int e2 = e - Em;
           r = __ldg(ar + e2) + nm;           c = __ldg(ac + e2) + nm;    v = __ldg(av + e2); }
    int pos = atomicAdd(&cursor[r], 1);
    edges[pos] = ((ull)__float_as_uint(v) << 32) | (unsigned)(c * (D * 4));
}

// -------------------- CSR SpMM, warp per row, fused acc --------------------
__global__ void k_spmm_csr(const ull* __restrict__ edges, const int* __restrict__ rowptr,
                           const float* __restrict__ x, const float* __restrict__ accin,
                           float* __restrict__ xnew, float* __restrict__ accout, int N) {
    int r = (blockIdx.x * blockDim.x + threadIdx.x) >> 5;
    if (r >= N) return;
    int lane = threadIdx.x & 31;

    int s = __ldg(rowptr + r);
    int e = __ldg(rowptr + r + 1);

    const char* xb = (const char*)x + lane * 8;   // lane byte base

    float ax = 0.f, ay = 0.f;
    #pragma unroll 4
    for (int i = s; i < e; i++) {
        ull p = __ldg(edges + i);                 // uniform per-warp broadcast
        unsigned off = (unsigned)p;               // pre-scaled byte offset
        float v = __uint_as_float((unsigned)(p >> 32));
        float2 xv = __ldg((const float2*)(xb + off));
        ax = fmaf(v, xv.x, ax);
        ay = fmaf(v, xv.y, ay);
    }

    float2 base = __ldg((const float2*)(accin + (size_t)r * D) + lane);
    if (xnew) ((float2*)(xnew + (size_t)r * D))[lane] = make_float2(ax, ay);
    ((float2*)(accout + (size_t)r * D))[lane] = make_float2(base.x + ax, base.y + ay);
}

// -------------------- Text GEMM (f32x2 packed) + fused l2norms + combine --------------------
// Block 256 threads, tile 64 rows x 64 cols, thread tile 4x4.
// K paired: A row-major [row][k], B transposed [col][k] (stride 72), acc = (even-k, odd-k).
#define BSTRIDE 72
__global__ void k_textfinal(const float* __restrict__ tm, const float* __restrict__ ta,
                            const float* __restrict__ W, const float* __restrict__ bias,
                            float* __restrict__ out, int N_M, int N_A) {
    __shared__ float As[64 * 64];          // [row][k]
    __shared__ float BsT[64 * BSTRIDE];    // [col][k], padded
    __shared__ float s_bias[64];
    __shared__ float s_nt[64];
    __shared__ float s_ng[64];

    const float* T;
    float* acc;
    int N;
    if (blockIdx.y == 0) { T = tm; acc = out;                   N = N_M; }
    else                 { T = ta; acc = out + (size_t)N_M * D; N = N_A; }

    int r0 = blockIdx.x * 64;
    if (r0 >= N) return;

    int tid = threadIdx.x;
    int tc  = tid & 15;       // fast lane dim -> B lane-varying, A broadcast
    int tr  = tid >> 4;

    if (tid < 64) { s_bias[tid] = bias[tid]; s_nt[tid] = 0.f; s_ng[tid] = 0.f; }

    ull accp[4][4];
    #pragma unroll
    for (int i = 0; i < 4; i++)
        #pragma unroll
        for (int j = 0; j < 4; j++) accp[i][j] = 0ull;

    for (int k0 = 0; k0 < DTXT; k0 += 64) {
        // A tile: 64 rows x 64 k (row-major)
        #pragma unroll
        for (int it = 0; it < 4; it++) {
            int fi = tid + it * 256;          // 0..1023 float4 slots
            int rr = fi >> 4;
            int kq = fi & 15;
            int gr = r0 + rr;
            float4 v = (gr < N) ? __ldg(((const float4*)(T + (size_t)gr * DTXT + k0)) + kq)
                                : make_float4(0.f, 0.f, 0.f, 0.f);
            ((float4*)As)[fi] = v;
        }
        // B tile transposed: BsT[col][k], coalesced global reads
        #pragma unroll
        for (int it = 0; it < 4; it++) {
            int idx = tid + it * 256;         // 0..1023 = 64 cols x 16 kq
            int col = idx & 63;
            int kq  = idx >> 6;
            float w0 = __ldg(W + (size_t)(k0 + kq * 4 + 0) * D + col);
            float w1 = __ldg(W + (size_t)(k0 + kq * 4 + 1) * D + col);
            float w2 = __ldg(W + (size_t)(k0 + kq * 4 + 2) * D + col);
            float w3 = __ldg(W + (size_t)(k0 + kq * 4 + 3) * D + col);
            *(float4*)(BsT + col * BSTRIDE + kq * 4) = make_float4(w0, w1, w2, w3);
        }
        __syncthreads();

        #pragma unroll
        for (int kk = 0; kk < 64; kk += 4) {
            ulonglong2 a[4], b[4];
            #pragma unroll
            for (int i = 0; i < 4; i++)
                a[i] = *(const ulonglong2*)(As + (tr * 4 + i) * 64 + kk);
            #pragma unroll
            for (int j = 0; j < 4; j++)
                b[j] = *(const ulonglong2*)(BsT + (tc * 4 + j) * BSTRIDE + kk);
            #pragma unroll
            for (int i = 0; i < 4; i++)
                #pragma unroll
                for (int j = 0; j < 4; j++) {
                    accp[i][j] = fma2(a[i].x, b[j].x, accp[i][j]);
                    accp[i][j] = fma2(a[i].y, b[j].y, accp[i][j]);
                }
        }
        __syncthreads();
    }

    // Epilogue: t = lo+hi+bias, row sumsq of t and g, then 0.5*(g/||g|| + t/||t||)
    float tv[4][4], gv[4][4];
    #pragma unroll
    for (int i = 0; i < 4; i++) {
        int lr = tr * 4 + i;
        int gr = r0 + lr;
        bool ok = gr < N;
        float st = 0.f, sg = 0.f;
        #pragma unroll
        for (int j = 0; j < 4; j++) {
            int c = tc * 4 + j;
            float lo = __uint_as_float((unsigned)accp[i][j]);
            float hi = __uint_as_float((unsigned)(accp[i][j] >> 32));
            float t = lo + hi + s_bias[c];
            tv[i][j] = t;
            st += t * t;
            float g = ok ? acc[(size_t)gr * D + c] : 0.f;
            gv[i][j] = g;
            sg += g * g;
        }
        if (ok) {
            atomicAdd(&s_nt[lr], st);
            atomicAdd(&s_ng[lr], sg);
        }
    }
    __syncthreads();

    #pragma unroll
    for (int i = 0; i < 4; i++) {
        int lr = tr * 4 + i;
        int gr = r0 + lr;
        if (gr >= N) continue;
        float int_ = 1.f / fmaxf(sqrtf(s_nt[lr]), 1e-12f);
        float ing  = 1.f / fmaxf(sqrtf(s_ng[lr]), 1e-12f);
        #pragma unroll
        for (int j = 0; j < 4; j++) {
            int c = tc * 4 + j;
            acc[(size_t)gr * D + c] = 0.5f * (gv[i][j] * ing + tv[i][j] * int_);
        }
    }
}

// -------------------- launch --------------------
extern "C" void kernel_launch(void* const* d_in, const int* in_sizes, int n_in,
                              void* d_out, int out_size) {
    const int*   m_row = (const int*)d_in[0];
    const int*   m_col = (const int*)d_in[1];
    const float* m_val = (const float*)d_in[2];
    const int*   a_row = (const int*)d_in[3];
    const int*   a_col = (const int*)d_in[4];
    const float* a_val = (const float*)d_in[5];
    const float* m_txt = (const float*)d_in[6];
    const float* a_txt = (const float*)d_in[7];
    const float* m_emb = (const float*)d_in[8];
    const float* a_emb = (const float*)d_in[9];
    const float* W     = (const float*)d_in[10];
    const float* bias  = (const float*)d_in[11];

    int E_M = in_sizes[0];
    int E_A = in_sizes[3];
    int N_M = in_sizes[8] / D;
    int N_A = in_sizes[9] / D;
    int Nt  = N_M + N_A;
    int Et  = E_M + E_A;

    float* out = (float*)d_out;

    ull*   edges;  cudaGetSymbolAddress((void**)&edges,  g_edges);
    float* bufA;   cudaGetSymbolAddress((void**)&bufA,   g_bufA);
    float* bufB;   cudaGetSymbolAddress((void**)&bufB,   g_bufB);
    int*   rowptr; cudaGetSymbolAddress((void**)&rowptr, g_rowptr);
    int*   cursor; cudaGetSymbolAddress((void**)&cursor, g_cursor);

    const int TB = 256;
    int eg  = (Et + TB - 1) / TB;
    int n4t = Nt * (D / 4);
    int cg  = (n4t + TB - 1) / TB;
    int sg  = (Nt * 32 + TB - 1) / TB;

    // combined CSR build
    cudaMemsetAsync(cursor, 0, (size_t)Nt * sizeof(int));
    k_copy2<<<cg, TB>>>((const float4*)m_emb, (const float4*)a_emb, (float4*)bufA,
                        N_M * (D / 4), n4t);
    k_hist2<<<eg, TB>>>(m_row, a_row, cursor, E_M, Et, N_M);
    k_scan<<<1, 1024>>>(cursor, rowptr, cursor, Nt);
    k_scatter2<<<eg, TB>>>(m_row, m_col, m_val, a_row, a_col, a_val,
                           cursor, edges, E_M, Et, N_M);

    // 3 propagation layers over both graphs at once (acc fused)
    k_spmm_csr<<<sg, TB>>>(edges, rowptr, bufA, bufA, bufB,      out, Nt); // acc = emb + x1
    k_spmm_csr<<<sg, TB>>>(edges, rowptr, bufB, out,  bufA,      out, Nt); // acc += x2
    k_spmm_csr<<<sg, TB>>>(edges, rowptr, bufA, out,  (float*)0, out, Nt); // acc += x3

    // text GEMM + norms + combine
    int maxN = (N_M > N_A) ? N_M : N_A;
    dim3 grid((maxN + 63) / 64, 2);
    k_textfinal<<<grid, 256>>>(m_txt, a_txt, W, bias, out, N_M, N_A);
}

// round 4
// speedup vs baseline: 1.0027x; 1.0027x over previous
#include <cuda_runtime.h>
#include <math.h>

#define D 64
#define DTXT 384
typedef unsigned long long ull;

#define MAXE (4 * 1024 * 1024)
#define MAXN 131072

// Scratch (static __device__ per harness rules)
__device__ ull   g_edges[MAXE];          // packed (val<<32 | col_byte_off), row-sorted
__device__ float g_bufA[MAXN * D];
__device__ float g_bufB[MAXN * D];
__device__ int   g_rowptr[MAXN + 1];
__device__ int   g_cursor[MAXN];

__device__ __forceinline__ ull fma2(ull a, ull b, ull c) {
    ull d;
    asm("fma.rn.f32x2 %0, %1, %2, %3;" : "=l"(d) : "l"(a), "l"(b), "l"(c));
    return d;
}

// -------------------- histogram --------------------
__global__ void k_hist(const int* __restrict__ row, int* __restrict__ cnt, int E) {
    int e = blockIdx.x * blockDim.x + threadIdx.x;
    if (e < E) atomicAdd(&cnt[__ldg(row + e)], 1);
}

// -------------------- single-block exclusive scan --------------------
__global__ void k_scan(const int* __restrict__ cnt, int* __restrict__ rowptr,
                       int* __restrict__ cursor, int N) {
    __shared__ int sp[1024];
    int tid = threadIdx.x;
    int chunk = (N + 1023) >> 10;
    int s = tid * chunk;
    int e = min(s + chunk, N);
    int sum = 0;
    for (int i = s; i < e; i++) sum += cnt[i];
    sp[tid] = sum;
    __syncthreads();
    for (int off = 1; off < 1024; off <<= 1) {
        int v = (tid >= off) ? sp[tid - off] : 0;
        __syncthreads();
        sp[tid] += v;
        __syncthreads();
    }
    int excl = (tid == 0) ? 0 : sp[tid - 1];
    for (int i = s; i < e; i++) {
        int c = cnt[i];          // read before overwrite (cnt aliases cursor)
        rowptr[i] = excl;
        cursor[i] = excl;
        excl += c;
    }
    if (tid == 0) rowptr[N] = sp[1023];
}

// -------------------- scatter edges into row-sorted order --------------------
__global__ void k_scatter(const int* __restrict__ row, const int* __restrict__ col,
                          const float* __restrict__ val, int* __restrict__ cursor,
                          ull* __restrict__ edges, int E) {
    int e = blockIdx.x * blockDim.x + threadIdx.x;
    if (e < E) {
        int r = __ldg(row + e);
        int pos = atomicAdd(&cursor[r], 1);
        ull p = ((ull)__float_as_uint(__ldg(val + e)) << 32)
              | (unsigned)(__ldg(col + e) * (D * 4));        // pre-scaled byte offset
        edges[pos] = p;
    }
}

// -------------------- CSR SpMM, warp per row, fused acc --------------------
__global__ void k_spmm_csr(const ull* __restrict__ edges, const int* __restrict__ rowptr,
                           const float* __restrict__ x, const float* __restrict__ accin,
                           float* __restrict__ xnew, float* __restrict__ accout, int N) {
    int r = (blockIdx.x * blockDim.x + threadIdx.x) >> 5;
    if (r >= N) return;
    int lane = threadIdx.x & 31;

    int s = __ldg(rowptr + r);
    int e = __ldg(rowptr + r + 1);

    const char* xb = (const char*)x + lane * 8;

    float ax = 0.f, ay = 0.f;
    #pragma unroll 4
    for (int i = s; i < e; i++) {
        ull p = __ldg(edges + i);                  // uniform per-warp broadcast
        unsigned off = (unsigned)p;                // byte offset, no IMAD needed
        float v = __uint_as_float((unsigned)(p >> 32));
        float2 xv = __ldg((const float2*)(xb + off));
        ax = fmaf(v, xv.x, ax);
        ay = fmaf(v, xv.y, ay);
    }

    float2 base = __ldg((const float2*)(accin + (size_t)r * D) + lane);
    if (xnew) ((float2*)(xnew + (size_t)r * D))[lane] = make_float2(ax, ay);
    ((float2*)(accout + (size_t)r * D))[lane] = make_float2(base.x + ax, base.y + ay);
}

// -------------------- Text GEMM (f32x2 packed) + fused l2norms + combine --------------------
#define BSTRIDE 72
__global__ void k_textfinal(const float* __restrict__ tm, const float* __restrict__ ta,
                            const float* __restrict__ W, const float* __restrict__ bias,
                            float* __restrict__ out, int N_M, int N_A) {
    __shared__ float As[64 * 64];          // [row][k]
    __shared__ float BsT[64 * BSTRIDE];    // [col][k], padded
    __shared__ float s_bias[64];
    __shared__ float s_nt[64];
    __shared__ float s_ng[64];

    const float* T;
    float* acc;
    int N;
    if (blockIdx.y == 0) { T = tm; acc = out;                   N = N_M; }
    else                 { T = ta; acc = out + (size_t)N_M * D; N = N_A; }

    int r0 = blockIdx.x * 64;
    if (r0 >= N) return;

    int tid = threadIdx.x;
    int tc  = tid & 15;
    int tr  = tid >> 4;

    if (tid < 64) { s_bias[tid] = bias[tid]; s_nt[tid] = 0.f; s_ng[tid] = 0.f; }

    ull accp[4][4];
    #pragma unroll
    for (int i = 0; i < 4; i++)
        #pragma unroll
        for (int j = 0; j < 4; j++) accp[i][j] = 0ull;

    for (int k0 = 0; k0 < DTXT; k0 += 64) {
        #pragma unroll
        for (int it = 0; it < 4; it++) {
            int fi = tid + it * 256;
            int rr = fi >> 4;
            int kq = fi & 15;
            int gr = r0 + rr;
            float4 v = (gr < N) ? __ldg(((const float4*)(T + (size_t)gr * DTXT + k0)) + kq)
                                : make_float4(0.f, 0.f, 0.f, 0.f);
            ((float4*)As)[fi] = v;
        }
        #pragma unroll
        for (int it = 0; it < 4; it++) {
            int idx = tid + it * 256;         // 64 cols x 16 kq
            int col = idx & 63;
            int kq  = idx >> 6;
            float w0 = __ldg(W + (size_t)(k0 + kq * 4 + 0) * D + col);
            float w1 = __ldg(W + (size_t)(k0 + kq * 4 + 1) * D + col);
            float w2 = __ldg(W + (size_t)(k0 + kq * 4 + 2) * D + col);
            float w3 = __ldg(W + (size_t)(k0 + kq * 4 + 3) * D + col);
            *(float4*)(BsT + col * BSTRIDE + kq * 4) = make_float4(w0, w1, w2, w3);
        }
        __syncthreads();

        #pragma unroll
        for (int kk = 0; kk < 64; kk += 4) {
            ulonglong2 a[4], b[4];
            #pragma unroll
            for (int i = 0; i < 4; i++)
                a[i] = *(const ulonglong2*)(As + (tr * 4 + i) * 64 + kk);
            #pragma unroll
            for (int j = 0; j < 4; j++)
                b[j] = *(const ulonglong2*)(BsT + (tc * 4 + j) * BSTRIDE + kk);
            #pragma unroll
            for (int i = 0; i < 4; i++)
                #pragma unroll
                for (int j = 0; j < 4; j++) {
                    accp[i][j] = fma2(a[i].x, b[j].x, accp[i][j]);
                    accp[i][j] = fma2(a[i].y, b[j].y, accp[i][j]);
                }
        }
        __syncthreads();
    }

    float tv[4][4], gv[4][4];
    #pragma unroll
    for (int i = 0; i < 4; i++) {
        int lr = tr * 4 + i;
        int gr = r0 + lr;
        bool ok = gr < N;
        float st = 0.f, sg = 0.f;
        #pragma unroll
        for (int j = 0; j < 4; j++) {
            int c = tc * 4 + j;
            float lo = __uint_as_float((unsigned)accp[i][j]);
            float hi = __uint_as_float((unsigned)(accp[i][j] >> 32));
            float t = lo + hi + s_bias[c];
            tv[i][j] = t;
            st += t * t;
            float g = ok ? acc[(size_t)gr * D + c] : 0.f;
            gv[i][j] = g;
            sg += g * g;
        }
        if (ok) {
            atomicAdd(&s_nt[lr], st);
            atomicAdd(&s_ng[lr], sg);
        }
    }
    __syncthreads();

    #pragma unroll
    for (int i = 0; i < 4; i++) {
        int lr = tr * 4 + i;
        int gr = r0 + lr;
        if (gr >= N) continue;
        float int_ = 1.f / fmaxf(sqrtf(s_nt[lr]), 1e-12f);
        float ing  = 1.f / fmaxf(sqrtf(s_ng[lr]), 1e-12f);
        #pragma unroll
        for (int j = 0; j < 4; j++) {
            int c = tc * 4 + j;
            acc[(size_t)gr * D + c] = 0.5f * (gv[i][j] * ing + tv[i][j] * int_);
        }
    }
}

// -------------------- launch --------------------
extern "C" void kernel_launch(void* const* d_in, const int* in_sizes, int n_in,
                              void* d_out, int out_size) {
    const int*   m_row = (const int*)d_in[0];
    const int*   m_col = (const int*)d_in[1];
    const float* m_val = (const float*)d_in[2];
    const int*   a_row = (const int*)d_in[3];
    const int*   a_col = (const int*)d_in[4];
    const float* a_val = (const float*)d_in[5];
    const float* m_txt = (const float*)d_in[6];
    const float* a_txt = (const float*)d_in[7];
    const float* m_emb = (const float*)d_in[8];
    const float* a_emb = (const float*)d_in[9];
    const float* W     = (const float*)d_in[10];
    const float* bias  = (const float*)d_in[11];

    int E_M = in_sizes[0];
    int E_A = in_sizes[3];
    int N_M = in_sizes[8] / D;
    int N_A = in_sizes[9] / D;

    float* out = (float*)d_out;

    ull*   edges;  cudaGetSymbolAddress((void**)&edges,  g_edges);
    float* bufA;   cudaGetSymbolAddress((void**)&bufA,   g_bufA);
    float* bufB;   cudaGetSymbolAddress((void**)&bufB,   g_bufB);
    int*   rowptr; cudaGetSymbolAddress((void**)&rowptr, g_rowptr);
    int*   cursor; cudaGetSymbolAddress((void**)&cursor, g_cursor);

    const int TB = 256;

    auto run_graph = [&](const int* row, const int* col, const float* val,
                         const float* emb, float* accout, int N, int E) {
        int eg = (E + TB - 1) / TB;
        int sg = (N * 32 + TB - 1) / TB;

        cudaMemsetAsync(cursor, 0, (size_t)N * sizeof(int));
        k_hist<<<eg, TB>>>(row, cursor, E);
        k_scan<<<1, 1024>>>(cursor, rowptr, cursor, N);
        k_scatter<<<eg, TB>>>(row, col, val, cursor, edges, E);

        k_spmm_csr<<<sg, TB>>>(edges, rowptr, emb,  emb,    bufA,      accout, N); // acc = emb + x1
        k_spmm_csr<<<sg, TB>>>(edges, rowptr, bufA, accout, bufB,      accout, N); // acc += x2
        k_spmm_csr<<<sg, TB>>>(edges, rowptr, bufB, accout, (float*)0, accout, N); // acc += x3
    };

    run_graph(m_row, m_col, m_val, m_emb, out,                   N_M, E_M);
    run_graph(a_row, a_col, a_val, a_emb, out + (size_t)N_M * D, N_A, E_A);

    int maxN = (N_M > N_A) ? N_M : N_A;
    dim3 grid((maxN + 63) / 64, 2);
    k_textfinal<<<grid, 256>>>(m_txt, a_txt, W, bias, out, N_M, N_A);
}

// round 5
// speedup vs baseline: 2.0921x; 2.0864x over previous
#include <cuda_runtime.h>
#include <math.h>

#define D 64
#define DTXT 384
typedef unsigned long long ull;

#define MAXE (4 * 1024 * 1024)
#define MAXN 131072

// Scratch (static __device__ per harness rules)
__device__ ull   g_edges[MAXE];          // packed (val<<32 | col_byte_off), row-sorted
__device__ float g_bufA[MAXN * D];
__device__ float g_bufB[MAXN * D];
__device__ int   g_rowptr[MAXN + 1];
__device__ int   g_cursor[MAXN];

// -------------------- histogram --------------------
__global__ void k_hist(const int* __restrict__ row, int* __restrict__ cnt, int E) {
    int e = blockIdx.x * blockDim.x + threadIdx.x;
    if (e < E) atomicAdd(&cnt[__ldg(row + e)], 1);
}

// -------------------- single-block exclusive scan --------------------
__global__ void k_scan(const int* __restrict__ cnt, int* __restrict__ rowptr,
                       int* __restrict__ cursor, int N) {
    __shared__ int sp[1024];
    int tid = threadIdx.x;
    int chunk = (N + 1023) >> 10;
    int s = tid * chunk;
    int e = min(s + chunk, N);
    int sum = 0;
    for (int i = s; i < e; i++) sum += cnt[i];
    sp[tid] = sum;
    __syncthreads();
    for (int off = 1; off < 1024; off <<= 1) {
        int v = (tid >= off) ? sp[tid - off] : 0;
        __syncthreads();
        sp[tid] += v;
        __syncthreads();
    }
    int excl = (tid == 0) ? 0 : sp[tid - 1];
    for (int i = s; i < e; i++) {
        int c = cnt[i];          // read before overwrite (cnt aliases cursor)
        rowptr[i] = excl;
        cursor[i] = excl;
        excl += c;
    }
    if (tid == 0) rowptr[N] = sp[1023];
}

// -------------------- scatter edges into row-sorted order --------------------
__global__ void k_scatter(const int* __restrict__ row, const int* __restrict__ col,
                          const float* __restrict__ val, int* __restrict__ cursor,
                          ull* __restrict__ edges, int E) {
    int e = blockIdx.x * blockDim.x + threadIdx.x;
    if (e < E) {
        int r = __ldg(row + e);
        int pos = atomicAdd(&cursor[r], 1);
        ull p = ((ull)__float_as_uint(__ldg(val + e)) << 32)
              | (unsigned)(__ldg(col + e) * (D * 4));
        edges[pos] = p;
    }
}

// -------------------- CSR SpMM, warp per row, fused acc (verified 67us) --------------------
__global__ void k_spmm_csr(const ull* __restrict__ edges, const int* __restrict__ rowptr,
                           const float* __restrict__ x, const float* __restrict__ accin,
                           float* __restrict__ xnew, float* __restrict__ accout, int N) {
    int r = (blockIdx.x * blockDim.x + threadIdx.x) >> 5;
    if (r >= N) return;
    int lane = threadIdx.x & 31;

    int s = __ldg(rowptr + r);
    int e = __ldg(rowptr + r + 1);

    const char* xb = (const char*)x + lane * 8;

    float ax = 0.f, ay = 0.f;
    #pragma unroll 4
    for (int i = s; i < e; i++) {
        ull p = __ldg(edges + i);
        unsigned off = (unsigned)p;
        float v = __uint_as_float((unsigned)(p >> 32));
        float2 xv = __ldg((const float2*)(xb + off));
        ax = fmaf(v, xv.x, ax);
        ay = fmaf(v, xv.y, ay);
    }

    float2 base = __ldg((const float2*)(accin + (size_t)r * D) + lane);
    if (xnew) ((float2*)(xnew + (size_t)r * D))[lane] = make_float2(ax, ay);
    ((float2*)(accout + (size_t)r * D))[lane] = make_float2(base.x + ax, base.y + ay);
}

// -------------------- tf32 helpers --------------------
__device__ __forceinline__ unsigned f2tf32(float v) {
    unsigned r;
    asm("cvt.rna.tf32.f32 %0, %1;" : "=r"(r) : "f"(v));
    return r;
}

#define MMA_TF32(c0,c1,c2,c3,a0,a1,a2,a3,b0,b1)                                     \
    asm volatile("mma.sync.aligned.m16n8k8.row.col.f32.tf32.tf32.f32 "              \
                 "{%0,%1,%2,%3},{%4,%5,%6,%7},{%8,%9},{%0,%1,%2,%3};"               \
                 : "+f"(c0), "+f"(c1), "+f"(c2), "+f"(c3)                           \
                 : "r"(a0), "r"(a1), "r"(a2), "r"(a3), "r"(b0), "r"(b1))

// -------------------- Text GEMM (tf32 HMMA) + fused l2norms + combine --------------------
// Block 256 thr (8 warps). Tile 64 rows x 64 cols. Warp = 16 rows x 32 cols
// (warpRow = wid>>1, warpCol = wid&1); 4 n-tiles of m16n8 per warp; k8 chunks.
#define ASTR 68   // conflict-free A-frag LDS
#define BSTR 72   // conflict-free B-frag LDS
__global__ void k_textfinal(const float* __restrict__ tm, const float* __restrict__ ta,
                            const float* __restrict__ W, const float* __restrict__ bias,
                            float* __restrict__ out, int N_M, int N_A) {
    __shared__ unsigned As[64 * ASTR];
    __shared__ unsigned Bs[64 * BSTR];
    __shared__ float s_bias[64];
    __shared__ float s_nt[64];
    __shared__ float s_ng[64];

    const float* T;
    float* acc;
    int N;
    if (blockIdx.y == 0) { T = tm; acc = out;                   N = N_M; }
    else                 { T = ta; acc = out + (size_t)N_M * D; N = N_A; }

    int r0 = blockIdx.x * 64;
    if (r0 >= N) return;

    int tid  = threadIdx.x;
    int wid  = tid >> 5;
    int lane = tid & 31;
    int gid  = lane >> 2;     // group id 0..7
    int tig  = lane & 3;      // thread in group 0..3
    int wr   = (wid >> 1) * 16;   // warp row base within tile
    int wc   = (wid & 1) * 32;    // warp col base within tile

    if (tid < 64) { s_bias[tid] = bias[tid]; s_nt[tid] = 0.f; s_ng[tid] = 0.f; }

    float c[4][4];
    #pragma unroll
    for (int j = 0; j < 4; j++)
        #pragma unroll
        for (int q = 0; q < 4; q++) c[j][q] = 0.f;

    for (int k0 = 0; k0 < DTXT; k0 += 64) {
        // A tile: 64 rows x 64 k, tf32-converted, stride ASTR (scalar STS)
        #pragma unroll
        for (int it = 0; it < 4; it++) {
            int fi = tid + it * 256;        // 1024 float4 slots
            int rr = fi >> 4;
            int kq = fi & 15;
            int gr = r0 + rr;
            float4 v = (gr < N) ? __ldg(((const float4*)(T + (size_t)gr * DTXT + k0)) + kq)
                                : make_float4(0.f, 0.f, 0.f, 0.f);
            unsigned* dst = As + rr * ASTR + kq * 4;
            dst[0] = f2tf32(v.x); dst[1] = f2tf32(v.y);
            dst[2] = f2tf32(v.z); dst[3] = f2tf32(v.w);
        }
        // B tile: 64 k x 64 cols, tf32-converted, stride BSTR
        #pragma unroll
        for (int it = 0; it < 4; it++) {
            int fi = tid + it * 256;
            int kk = fi >> 4;
            int cq = fi & 15;
            float4 v = __ldg(((const float4*)(W + (size_t)(k0 + kk) * D)) + cq);
            unsigned* dst = Bs + kk * BSTR + cq * 4;
            dst[0] = f2tf32(v.x); dst[1] = f2tf32(v.y);
            dst[2] = f2tf32(v.z); dst[3] = f2tf32(v.w);
        }
        __syncthreads();

        #pragma unroll
        for (int kk = 0; kk < 64; kk += 8) {
            unsigned a0 = As[(wr + gid)     * ASTR + kk + tig];
            unsigned a1 = As[(wr + gid + 8) * ASTR + kk + tig];
            unsigned a2 = As[(wr + gid)     * ASTR + kk + tig + 4];
            unsigned a3 = As[(wr + gid + 8) * ASTR + kk + tig + 4];
            #pragma unroll
            for (int j = 0; j < 4; j++) {
                int cb = wc + j * 8;
                unsigned b0 = Bs[(kk + tig)     * BSTR + cb + gid];
                unsigned b1 = Bs[(kk + tig + 4) * BSTR + cb + gid];
                MMA_TF32(c[j][0], c[j][1], c[j][2], c[j][3], a0, a1, a2, a3, b0, b1);
            }
        }
        __syncthreads();
    }

    // Epilogue. Thread owns rows rA = wr+gid, rB = wr+gid+8; cols cb+2*tig, +1 per n-tile.
    int lrA = wr + gid, lrB = lrA + 8;
    int grA = r0 + lrA, grB = r0 + lrB;
    bool okA = grA < N, okB = grB < N;

    float tv[4][4];
    float2 gA[4], gB[4];
    float stA = 0.f, stB = 0.f, sgA = 0.f, sgB = 0.f;
    #pragma unroll
    for (int j = 0; j < 4; j++) {
        int col = wc + j * 8 + 2 * tig;
        float b0 = s_bias[col], b1 = s_bias[col + 1];
        float t0 = c[j][0] + b0, t1 = c[j][1] + b1;   // row A
        float t2 = c[j][2] + b0, t3 = c[j][3] + b1;   // row B
        tv[j][0] = t0; tv[j][1] = t1; tv[j][2] = t2; tv[j][3] = t3;
        stA += t0 * t0 + t1 * t1;
        stB += t2 * t2 + t3 * t3;
        float2 ga = okA ? *(const float2*)(acc + (size_t)grA * D + col) : make_float2(0.f, 0.f);
        float2 gb = okB ? *(const float2*)(acc + (size_t)grB * D + col) : make_float2(0.f, 0.f);
        gA[j] = ga; gB[j] = gb;
        sgA += ga.x * ga.x + ga.y * ga.y;
        sgB += gb.x * gb.x + gb.y * gb.y;
    }
    // butterfly over the 4-lane group (lanes share gid)
    #pragma unroll
    for (int m = 1; m < 4; m <<= 1) {
        stA += __shfl_xor_sync(0xffffffffu, stA, m);
        stB += __shfl_xor_sync(0xffffffffu, stB, m);
        sgA += __shfl_xor_sync(0xffffffffu, sgA, m);
        sgB += __shfl_xor_sync(0xffffffffu, sgB, m);
    }
    if (tig == 0) {
        atomicAdd(&s_nt[lrA], stA);
        atomicAdd(&s_nt[lrB], stB);
        atomicAdd(&s_ng[lrA], sgA);
        atomicAdd(&s_ng[lrB], sgB);
    }
    __syncthreads();

    float intA = 1.f / fmaxf(sqrtf(s_nt[lrA]), 1e-12f);
    float intB = 1.f / fmaxf(sqrtf(s_nt[lrB]), 1e-12f);
    float ingA = 1.f / fmaxf(sqrtf(s_ng[lrA]), 1e-12f);
    float ingB = 1.f / fmaxf(sqrtf(s_ng[lrB]), 1e-12f);

    #pragma unroll
    for (int j = 0; j < 4; j++) {
        int col = wc + j * 8 + 2 * tig;
        if (okA)
            *(float2*)(acc + (size_t)grA * D + col) =
                make_float2(0.5f * (gA[j].x * ingA + tv[j][0] * intA),
                            0.5f * (gA[j].y * ingA + tv[j][1] * intA));
        if (okB)
            *(float2*)(acc + (size_t)grB * D + col) =
                make_float2(0.5f * (gB[j].x * ingB + tv[j][2] * intB),
                            0.5f * (gB[j].y * ingB + tv[j][3] * intB));
    }
}

// -------------------- launch --------------------
extern "C" void kernel_launch(void* const* d_in, const int* in_sizes, int n_in,
                              void* d_out, int out_size) {
    const int*   m_row = (const int*)d_in[0];
    const int*   m_col = (const int*)d_in[1];
    const float* m_val = (const float*)d_in[2];
    const int*   a_row = (const int*)d_in[3];
    const int*   a_col = (const int*)d_in[4];
    const float* a_val = (const float*)d_in[5];
    const float* m_txt = (const float*)d_in[6];
    const float* a_txt = (const float*)d_in[7];
    const float* m_emb = (const float*)d_in[8];
    const float* a_emb = (const float*)d_in[9];
    const float* W     = (const float*)d_in[10];
    const float* bias  = (const float*)d_in[11];

    int E_M = in_sizes[0];
    int E_A = in_sizes[3];
    int N_M = in_sizes[8] / D;
    int N_A = in_sizes[9] / D;

    float* out = (float*)d_out;

    ull*   edges;  cudaGetSymbolAddress((void**)&edges,  g_edges);
    float* bufA;   cudaGetSymbolAddress((void**)&bufA,   g_bufA);
    float* bufB;   cudaGetSymbolAddress((void**)&bufB,   g_bufB);
    int*   rowptr; cudaGetSymbolAddress((void**)&rowptr, g_rowptr);
    int*   cursor; cudaGetSymbolAddress((void**)&cursor, g_cursor);

    const int TB = 256;

    auto run_graph = [&](const int* row, const int* col, const float* val,
                         const float* emb, float* accout, int N, int E) {
        int eg = (E + TB - 1) / TB;
        int sg = (N * 32 + TB - 1) / TB;

        cudaMemsetAsync(cursor, 0, (size_t)N * sizeof(int));
        k_hist<<<eg, TB>>>(row, cursor, E);
        k_scan<<<1, 1024>>>(cursor, rowptr, cursor, N);
        k_scatter<<<eg, TB>>>(row, col, val, cursor, edges, E);

        k_spmm_csr<<<sg, TB>>>(edges, rowptr, emb,  emb,    bufA,      accout, N);
        k_spmm_csr<<<sg, TB>>>(edges, rowptr, bufA, accout, bufB,      accout, N);
        k_spmm_csr<<<sg, TB>>>(edges, rowptr, bufB, accout, (float*)0, accout, N);
    };

    run_graph(m_row, m_col, m_val, m_emb, out,                   N_M, E_M);
    run_graph(a_row, a_col, a_val, a_emb, out + (size_t)N_M * D, N_A, E_A);

    int maxN = (N_M > N_A) ? N_M : N_A;
    dim3 grid((maxN + 63) / 64, 2);
    k_textfinal<<<grid, 256>>>(m_txt, a_txt, W, bias, out, N_M, N_A);
}

// round 6
// speedup vs baseline: 2.5245x; 1.2067x over previous
#include <cuda_runtime.h>
#include <math.h>

#define D 64
#define DTXT 384
typedef unsigned long long ull;

#define MAXE (4 * 1024 * 1024)
#define MAXN 131072

// Scratch (static __device__ per harness rules)
__device__ ull   g_edgesM[MAXE];
__device__ ull   g_edgesA[MAXE];
__device__ float g_bufA[MAXN * D];
__device__ float g_bufB[MAXN * D];
__device__ int   g_rowptrM[MAXN + 1];
__device__ int   g_rowptrA[MAXN + 1];
__device__ int   g_cnt[2 * MAXN];          // cursors: [0..MAXN) = M, [MAXN..) = A
__device__ float g_wt[DTXT * D];           // W pre-converted to tf32 (rna), fp32 bit layout

// -------------------- W -> tf32 (rna), once --------------------
__global__ void k_prepw(const float* __restrict__ W, float* __restrict__ wt, int n) {
    int i = blockIdx.x * blockDim.x + threadIdx.x;
    if (i < n) {
        unsigned r;
        asm("cvt.rna.tf32.f32 %0, %1;" : "=r"(r) : "f"(W[i]));
        wt[i] = __uint_as_float(r);
    }
}

// -------------------- fused histogram over both graphs --------------------
__global__ void k_hist2(const int* __restrict__ mr, const int* __restrict__ ar,
                        int* __restrict__ cntM, int* __restrict__ cntA, int Em, int Et) {
    int e = blockIdx.x * blockDim.x + threadIdx.x;
    if (e >= Et) return;
    if (e < Em) atomicAdd(&cntM[__ldg(mr + e)], 1);
    else        atomicAdd(&cntA[__ldg(ar + e - Em)], 1);
}

// -------------------- 2-block scan: block b scans graph b --------------------
__global__ void k_scan2(int* __restrict__ cntM, int* __restrict__ rpM,
                        int* __restrict__ cntA, int* __restrict__ rpA, int N) {
    __shared__ int sp[1024];
    int* cnt     = (blockIdx.x == 0) ? cntM : cntA;   // aliases cursor
    int* rowptr  = (blockIdx.x == 0) ? rpM  : rpA;
    int tid = threadIdx.x;
    int chunk = (N + 1023) >> 10;
    int s = tid * chunk;
    int e = min(s + chunk, N);
    int sum = 0;
    for (int i = s; i < e; i++) sum += cnt[i];
    sp[tid] = sum;
    __syncthreads();
    for (int off = 1; off < 1024; off <<= 1) {
        int v = (tid >= off) ? sp[tid - off] : 0;
        __syncthreads();
        sp[tid] += v;
        __syncthreads();
    }
    int excl = (tid == 0) ? 0 : sp[tid - 1];
    for (int i = s; i < e; i++) {
        int c = cnt[i];          // read before overwrite
        rowptr[i] = excl;
        cnt[i]    = excl;        // becomes scatter cursor
        excl += c;
    }
    if (tid == 0) rowptr[N] = sp[1023];
}

// -------------------- fused scatter for both graphs --------------------
__global__ void k_scatter2(const int* __restrict__ mr, const int* __restrict__ mc,
                           const float* __restrict__ mv,
                           const int* __restrict__ ar, const int* __restrict__ ac,
                           const float* __restrict__ av,
                           int* __restrict__ curM, int* __restrict__ curA,
                           ull* __restrict__ edM, ull* __restrict__ edA,
                           int Em, int Et) {
    int e = blockIdx.x * blockDim.x + threadIdx.x;
    if (e >= Et) return;
    if (e < Em) {
        int r = __ldg(mr + e);
        int pos = atomicAdd(&curM[r], 1);
        edM[pos] = ((ull)__float_as_uint(__ldg(mv + e)) << 32)
                 | (unsigned)(__ldg(mc + e) * (D * 4));
    } else {
        int e2 = e - Em;
        int r = __ldg(ar + e2);
        int pos = atomicAdd(&curA[r], 1);
        edA[pos] = ((ull)__float_as_uint(__ldg(av + e2)) << 32)
                 | (unsigned)(__ldg(ac + e2) * (D * 4));
    }
}

// -------------------- CSR SpMM, warp per row, fused acc (verified 67us) --------------------
__global__ void k_spmm_csr(const ull* __restrict__ edges, const int* __restrict__ rowptr,
                           const float* __restrict__ x, const float* __restrict__ accin,
                           float* __restrict__ xnew, float* __restrict__ accout, int N) {
    int r = (blockIdx.x * blockDim.x + threadIdx.x) >> 5;
    if (r >= N) return;
    int lane = threadIdx.x & 31;

    int s = __ldg(rowptr + r);
    int e = __ldg(rowptr + r + 1);

    const char* xb = (const char*)x + lane * 8;

    float ax = 0.f, ay = 0.f;
    #pragma unroll 4
    for (int i = s; i < e; i++) {
        ull p = __ldg(edges + i);
        unsigned off = (unsigned)p;
        float v = __uint_as_float((unsigned)(p >> 32));
        float2 xv = __ldg((const float2*)(xb + off));
        ax = fmaf(v, xv.x, ax);
        ay = fmaf(v, xv.y, ay);
    }

    float2 base = __ldg((const float2*)(accin + (size_t)r * D) + lane);
    if (xnew) ((float2*)(xnew + (size_t)r * D))[lane] = make_float2(ax, ay);
    ((float2*)(accout + (size_t)r * D))[lane] = make_float2(base.x + ax, base.y + ay);
}

#define MMA_TF32(c0,c1,c2,c3,a0,a1,a2,a3,b0,b1)                                     \
    asm volatile("mma.sync.aligned.m16n8k8.row.col.f32.tf32.tf32.f32 "              \
                 "{%0,%1,%2,%3},{%4,%5,%6,%7},{%8,%9},{%0,%1,%2,%3};"               \
                 : "+f"(c0), "+f"(c1), "+f"(c2), "+f"(c3)                           \
                 : "r"(a0), "r"(a1), "r"(a2), "r"(a3), "r"(b0), "r"(b1))

// -------------------- Text GEMM (tf32 HMMA, raw-truncated A, pre-rounded B) --------------------
#define ASTR 68
#define BSTR 72
__global__ void k_textfinal(const float* __restrict__ tm, const float* __restrict__ ta,
                            const float* __restrict__ Wt, const float* __restrict__ bias,
                            float* __restrict__ out, int N_M, int N_A) {
    __shared__ float As[64 * ASTR];
    __shared__ float Bs[64 * BSTR];
    __shared__ float s_bias[64];
    __shared__ float s_nt[64];
    __shared__ float s_ng[64];

    const float* T;
    float* acc;
    int N;
    if (blockIdx.y == 0) { T = tm; acc = out;                   N = N_M; }
    else                 { T = ta; acc = out + (size_t)N_M * D; N = N_A; }

    int r0 = blockIdx.x * 64;
    if (r0 >= N) return;

    int tid  = threadIdx.x;
    int wid  = tid >> 5;
    int lane = tid & 31;
    int gid  = lane >> 2;
    int tig  = lane & 3;
    int wr   = (wid >> 1) * 16;
    int wc   = (wid & 1) * 32;

    if (tid < 64) { s_bias[tid] = bias[tid]; s_nt[tid] = 0.f; s_ng[tid] = 0.f; }

    float c[4][4];
    #pragma unroll
    for (int j = 0; j < 4; j++)
        #pragma unroll
        for (int q = 0; q < 4; q++) c[j][q] = 0.f;

    for (int k0 = 0; k0 < DTXT; k0 += 64) {
        // A tile: raw fp32 bits (HW truncates to tf32) — LDG.128 + STS.128
        #pragma unroll
        for (int it = 0; it < 4; it++) {
            int fi = tid + it * 256;
            int rr = fi >> 4;
            int kq = fi & 15;
            int gr = r0 + rr;
            float4 v = (gr < N) ? __ldg(((const float4*)(T + (size_t)gr * DTXT + k0)) + kq)
                                : make_float4(0.f, 0.f, 0.f, 0.f);
            *(float4*)(As + rr * ASTR + kq * 4) = v;
        }
        // B tile: pre-converted tf32 — LDG.128 + STS.128
        #pragma unroll
        for (int it = 0; it < 4; it++) {
            int fi = tid + it * 256;
            int kk = fi >> 4;
            int cq = fi & 15;
            float4 v = __ldg(((const float4*)(Wt + (size_t)(k0 + kk) * D)) + cq);
            *(float4*)(Bs + kk * BSTR + cq * 4) = v;
        }
        __syncthreads();

        #pragma unroll
        for (int kk = 0; kk < 64; kk += 8) {
            unsigned a0 = __float_as_uint(As[(wr + gid)     * ASTR + kk + tig]);
            unsigned a1 = __float_as_uint(As[(wr + gid + 8) * ASTR + kk + tig]);
            unsigned a2 = __float_as_uint(As[(wr + gid)     * ASTR + kk + tig + 4]);
            unsigned a3 = __float_as_uint(As[(wr + gid + 8) * ASTR + kk + tig + 4]);
            #pragma unroll
            for (int j = 0; j < 4; j++) {
                int cb = wc + j * 8;
                unsigned b0 = __float_as_uint(Bs[(kk + tig)     * BSTR + cb + gid]);
                unsigned b1 = __float_as_uint(Bs[(kk + tig + 4) * BSTR + cb + gid]);
                MMA_TF32(c[j][0], c[j][1], c[j][2], c[j][3], a0, a1, a2, a3, b0, b1);
            }
        }
        __syncthreads();
    }

    int lrA = wr + gid, lrB = lrA + 8;
    int grA = r0 + lrA, grB = r0 + lrB;
    bool okA = grA < N, okB = grB < N;

    float tv[4][4];
    float2 gA[4], gB[4];
    float stA = 0.f, stB = 0.f, sgA = 0.f, sgB = 0.f;
    #pragma unroll
    for (int j = 0; j < 4; j++) {
        int col = wc + j * 8 + 2 * tig;
        float b0 = s_bias[col], b1 = s_bias[col + 1];
        float t0 = c[j][0] + b0, t1 = c[j][1] + b1;
        float t2 = c[j][2] + b0, t3 = c[j][3] + b1;
        tv[j][0] = t0; tv[j][1] = t1; tv[j][2] = t2; tv[j][3] = t3;
        stA += t0 * t0 + t1 * t1;
        stB += t2 * t2 + t3 * t3;
        float2 ga = okA ? *(const float2*)(acc + (size_t)grA * D + col) : make_float2(0.f, 0.f);
        float2 gb = okB ? *(const float2*)(acc + (size_t)grB * D + col) : make_float2(0.f, 0.f);
        gA[j] = ga; gB[j] = gb;
        sgA += ga.x * ga.x + ga.y * ga.y;
        sgB += gb.x * gb.x + gb.y * gb.y;
    }
    #pragma unroll
    for (int m = 1; m < 4; m <<= 1) {
        stA += __shfl_xor_sync(0xffffffffu, stA, m);
        stB += __shfl_xor_sync(0xffffffffu, stB, m);
        sgA += __shfl_xor_sync(0xffffffffu, sgA, m);
        sgB += __shfl_xor_sync(0xffffffffu, sgB, m);
    }
    if (tig == 0) {
        atomicAdd(&s_nt[lrA], stA);
        atomicAdd(&s_nt[lrB], stB);
        atomicAdd(&s_ng[lrA], sgA);
        atomicAdd(&s_ng[lrB], sgB);
    }
    __syncthreads();

    float intA = 1.f / fmaxf(sqrtf(s_nt[lrA]), 1e-12f);
    float intB = 1.f / fmaxf(sqrtf(s_nt[lrB]), 1e-12f);
    float ingA = 1.f / fmaxf(sqrtf(s_ng[lrA]), 1e-12f);
    float ingB = 1.f / fmaxf(sqrtf(s_ng[lrB]), 1e-12f);

    #pragma unroll
    for (int j = 0; j < 4; j++) {
        int col = wc + j * 8 + 2 * tig;
        if (okA)
            *(float2*)(acc + (size_t)grA * D + col) =
                make_float2(0.5f * (gA[j].x * ingA + tv[j][0] * intA),
                            0.5f * (gA[j].y * ingA + tv[j][1] * intA));
        if (okB)
            *(float2*)(acc + (size_t)grB * D + col) =
                make_float2(0.5f * (gB[j].x * ingB + tv[j][2] * intB),
                            0.5f * (gB[j].y * ingB + tv[j][3] * intB));
    }
}

// -------------------- launch --------------------
extern "C" void kernel_launch(void* const* d_in, const int* in_sizes, int n_in,
                              void* d_out, int out_size) {
    const int*   m_row = (const int*)d_in[0];
    const int*   m_col = (const int*)d_in[1];
    const float* m_val = (const float*)d_in[2];
    const int*   a_row = (const int*)d_in[3];
    const int*   a_col = (const int*)d_in[4];
    const float* a_val = (const float*)d_in[5];
    const float* m_txt = (const float*)d_in[6];
    const float* a_txt = (const float*)d_in[7];
    const float* m_emb = (const float*)d_in[8];
    const float* a_emb = (const float*)d_in[9];
    const float* W     = (const float*)d_in[10];
    const float* bias  = (const float*)d_in[11];

    int E_M = in_sizes[0];
    int E_A = in_sizes[3];
    int N_M = in_sizes[8] / D;
    int N_A = in_sizes[9] / D;
    int Et  = E_M + E_A;

    float* out = (float*)d_out;
    float* outA = out + (size_t)N_M * D;

    ull*   edM;  cudaGetSymbolAddress((void**)&edM,  g_edgesM);
    ull*   edA;  cudaGetSymbolAddress((void**)&edA,  g_edgesA);
    float* bufA; cudaGetSymbolAddress((void**)&bufA, g_bufA);
    float* bufB; cudaGetSymbolAddress((void**)&bufB, g_bufB);
    int*   rpM;  cudaGetSymbolAddress((void**)&rpM,  g_rowptrM);
    int*   rpA;  cudaGetSymbolAddress((void**)&rpA,  g_rowptrA);
    int*   cnt;  cudaGetSymbolAddress((void**)&cnt,  g_cnt);
    float* wt;   cudaGetSymbolAddress((void**)&wt,   g_wt);

    int* cntM = cnt;
    int* cntA = cnt + MAXN;

    const int TB = 256;
    int eg  = (Et + TB - 1) / TB;
    int sgM = (N_M * 32 + TB - 1) / TB;
    int sgA = (N_A * 32 + TB - 1) / TB;

    // prep: W tf32 conversion + zero counters
    k_prepw<<<(DTXT * D + TB - 1) / TB, TB>>>(W, wt, DTXT * D);
    cudaMemsetAsync(cnt, 0, 2 * (size_t)MAXN * sizeof(int));

    // combined CSR builds
    k_hist2<<<eg, TB>>>(m_row, a_row, cntM, cntA, E_M, Et);
    k_scan2<<<2, 1024>>>(cntM, rpM, cntA, rpA, N_M);   // N_M == N_A
    k_scatter2<<<eg, TB>>>(m_row, m_col, m_val, a_row, a_col, a_val,
                           cntM, cntA, edM, edA, E_M, Et);

    // graph M propagation
    k_spmm_csr<<<sgM, TB>>>(edM, rpM, m_emb, m_emb, bufA,      out, N_M);
    k_spmm_csr<<<sgM, TB>>>(edM, rpM, bufA,  out,   bufB,      out, N_M);
    k_spmm_csr<<<sgM, TB>>>(edM, rpM, bufB,  out,   (float*)0, out, N_M);

    // graph A propagation
    k_spmm_csr<<<sgA, TB>>>(edA, rpA, a_emb, a_emb, bufA,      outA, N_A);
    k_spmm_csr<<<sgA, TB>>>(edA, rpA, bufA,  outA,  bufB,      outA, N_A);
    k_spmm_csr<<<sgA, TB>>>(edA, rpA, bufB,  outA,  (float*)0, outA, N_A);

    // text GEMM + norms + combine
    int maxN = (N_M > N_A) ? N_M : N_A;
    dim3 grid((maxN + 63) / 64, 2);
    k_textfinal<<<grid, 256>>>(m_txt, a_txt, wt, bias, out, N_M, N_A);
}

// round 7
// speedup vs baseline: 2.7278x; 1.0805x over previous
#include <cuda_runtime.h>
#include <math.h>

#define D 64
#define DTXT 384
typedef unsigned long long ull;

#define MAXE (4 * 1024 * 1024)
#define MAXN 131072

// Scratch (static __device__ per harness rules)
__device__ ull   g_edgesM[MAXE];
__device__ ull   g_edgesA[MAXE];
__device__ float g_bufA[MAXN * D];
__device__ float g_bufB[MAXN * D];
__device__ int   g_rowptrM[MAXN + 1];
__device__ int   g_rowptrA[MAXN + 1];
__device__ int   g_cnt[2 * MAXN];
__device__ float g_wt[DTXT * D];           // W pre-converted to tf32

// -------------------- W -> tf32 (rna), once --------------------
__global__ void k_prepw(const float* __restrict__ W, float* __restrict__ wt, int n) {
    int i = blockIdx.x * blockDim.x + threadIdx.x;
    if (i < n) {
        unsigned r;
        asm("cvt.rna.tf32.f32 %0, %1;" : "=r"(r) : "f"(W[i]));
        wt[i] = __uint_as_float(r);
    }
}

// -------------------- histogram, 4 edges/thread (MLP=4), blockIdx.y = graph --------------------
__global__ void k_hist4(const int* __restrict__ mr, const int* __restrict__ ar,
                        int* __restrict__ cntM, int* __restrict__ cntA,
                        int Em, int Ea) {
    const int* rowp; int* cnt; int E;
    if (blockIdx.y == 0) { rowp = mr; cnt = cntM; E = Em; }
    else                 { rowp = ar; cnt = cntA; E = Ea; }
    int e0 = (blockIdx.x * blockDim.x + threadIdx.x) * 4;
    if (e0 + 3 < E) {
        int4 r = __ldg((const int4*)(rowp + e0));
        atomicAdd(&cnt[r.x], 1);
        atomicAdd(&cnt[r.y], 1);
        atomicAdd(&cnt[r.z], 1);
        atomicAdd(&cnt[r.w], 1);
    } else {
        for (int k = 0; k < 4; k++)
            if (e0 + k < E) atomicAdd(&cnt[__ldg(rowp + e0 + k)], 1);
    }
}

// -------------------- 2-block scan: block b scans graph b --------------------
__global__ void k_scan2(int* __restrict__ cntM, int* __restrict__ rpM,
                        int* __restrict__ cntA, int* __restrict__ rpA, int N) {
    __shared__ int sp[1024];
    int* cnt    = (blockIdx.x == 0) ? cntM : cntA;
    int* rowptr = (blockIdx.x == 0) ? rpM  : rpA;
    int tid = threadIdx.x;
    int chunk = (N + 1023) >> 10;
    int s = tid * chunk;
    int e = min(s + chunk, N);
    int sum = 0;
    for (int i = s; i < e; i++) sum += cnt[i];
    sp[tid] = sum;
    __syncthreads();
    for (int off = 1; off < 1024; off <<= 1) {
        int v = (tid >= off) ? sp[tid - off] : 0;
        __syncthreads();
        sp[tid] += v;
        __syncthreads();
    }
    int excl = (tid == 0) ? 0 : sp[tid - 1];
    for (int i = s; i < e; i++) {
        int c = cnt[i];          // read before overwrite (cnt aliases cursor)
        rowptr[i] = excl;
        cnt[i]    = excl;
        excl += c;
    }
    if (tid == 0) rowptr[N] = sp[1023];
}

// -------------------- scatter, 4 edges/thread (MLP=4), blockIdx.y = graph --------------------
__global__ void k_scatter4(const int* __restrict__ mr, const int* __restrict__ mc,
                           const float* __restrict__ mv,
                           const int* __restrict__ ar, const int* __restrict__ ac,
                           const float* __restrict__ av,
                           int* __restrict__ curM, int* __restrict__ curA,
                           ull* __restrict__ edM, ull* __restrict__ edA,
                           int Em, int Ea) {
    const int* rowp; const int* colp; const float* valp; int* cur; ull* ed; int E;
    if (blockIdx.y == 0) { rowp = mr; colp = mc; valp = mv; cur = curM; ed = edM; E = Em; }
    else                 { rowp = ar; colp = ac; valp = av; cur = curA; ed = edA; E = Ea; }
    int e0 = (blockIdx.x * blockDim.x + threadIdx.x) * 4;
    if (e0 + 3 < E) {
        int4   r = __ldg((const int4*)(rowp + e0));
        int4   c = __ldg((const int4*)(colp + e0));
        float4 v = __ldg((const float4*)(valp + e0));
        int p0 = atomicAdd(&cur[r.x], 1);
        int p1 = atomicAdd(&cur[r.y], 1);
        int p2 = atomicAdd(&cur[r.z], 1);
        int p3 = atomicAdd(&cur[r.w], 1);
        ed[p0] = ((ull)__float_as_uint(v.x) << 32) | (unsigned)(c.x * (D * 4));
        ed[p1] = ((ull)__float_as_uint(v.y) << 32) | (unsigned)(c.y * (D * 4));
        ed[p2] = ((ull)__float_as_uint(v.z) << 32) | (unsigned)(c.z * (D * 4));
        ed[p3] = ((ull)__float_as_uint(v.w) << 32) | (unsigned)(c.w * (D * 4));
    } else {
        for (int k = 0; k < 4; k++) {
            int e = e0 + k;
            if (e < E) {
                int r = __ldg(rowp + e);
                int pos = atomicAdd(&cur[r], 1);
                ed[pos] = ((ull)__float_as_uint(__ldg(valp + e)) << 32)
                        | (unsigned)(__ldg(colp + e) * (D * 4));
            }
        }
    }
}

// -------------------- CSR SpMM: half-warp per row, float4 lanes, fused acc --------------------
__global__ void k_spmm_csr(const ull* __restrict__ edges, const int* __restrict__ rowptr,
                           const float* __restrict__ x, const float* __restrict__ accin,
                           float* __restrict__ xnew, float* __restrict__ accout, int N) {
    int tid = blockIdx.x * blockDim.x + threadIdx.x;
    int r = tid >> 4;                   // half-warp per row
    if (r >= N) return;
    int lane16 = threadIdx.x & 15;

    int s = __ldg(rowptr + r);
    int e = __ldg(rowptr + r + 1);

    const char* xb = (const char*)x + lane16 * 16;

    float ax = 0.f, ay = 0.f, az = 0.f, aw = 0.f;
    #pragma unroll 4
    for (int i = s; i < e; i++) {
        ull p = __ldg(edges + i);                  // broadcast to 16 lanes
        unsigned off = (unsigned)p;                // pre-scaled row byte offset
        float v = __uint_as_float((unsigned)(p >> 32));
        float4 xv = __ldg((const float4*)(xb + off));
        ax = fmaf(v, xv.x, ax);
        ay = fmaf(v, xv.y, ay);
        az = fmaf(v, xv.z, az);
        aw = fmaf(v, xv.w, aw);
    }

    float4 base = __ldg((const float4*)(accin + (size_t)r * D) + lane16);
    if (xnew) ((float4*)(xnew + (size_t)r * D))[lane16] = make_float4(ax, ay, az, aw);
    ((float4*)(accout + (size_t)r * D))[lane16] =
        make_float4(base.x + ax, base.y + ay, base.z + az, base.w + aw);
}

#define MMA_TF32(c0,c1,c2,c3,a0,a1,a2,a3,b0,b1)                                     \
    asm volatile("mma.sync.aligned.m16n8k8.row.col.f32.tf32.tf32.f32 "              \
                 "{%0,%1,%2,%3},{%4,%5,%6,%7},{%8,%9},{%0,%1,%2,%3};"               \
                 : "+f"(c0), "+f"(c1), "+f"(c2), "+f"(c3)                           \
                 : "r"(a0), "r"(a1), "r"(a2), "r"(a3), "r"(b0), "r"(b1))

// -------------------- Text GEMM (tf32 HMMA) + fused l2norms + combine --------------------
#define ASTR 68
#define BSTR 72
__global__ void k_textfinal(const float* __restrict__ tm, const float* __restrict__ ta,
                            const float* __restrict__ Wt, const float* __restrict__ bias,
                            float* __restrict__ out, int N_M, int N_A) {
    __shared__ float As[64 * ASTR];
    __shared__ float Bs[64 * BSTR];
    __shared__ float s_bias[64];
    __shared__ float s_nt[64];
    __shared__ float s_ng[64];

    const float* T;
    float* acc;
    int N;
    if (blockIdx.y == 0) { T = tm; acc = out;                   N = N_M; }
    else                 { T = ta; acc = out + (size_t)N_M * D; N = N_A; }

    int r0 = blockIdx.x * 64;
    if (r0 >= N) return;

    int tid  = threadIdx.x;
    int wid  = tid >> 5;
    int lane = tid & 31;
    int gid  = lane >> 2;
    int tig  = lane & 3;
    int wr   = (wid >> 1) * 16;
    int wc   = (wid & 1) * 32;

    if (tid < 64) { s_bias[tid] = bias[tid]; s_nt[tid] = 0.f; s_ng[tid] = 0.f; }

    float c[4][4];
    #pragma unroll
    for (int j = 0; j < 4; j++)
        #pragma unroll
        for (int q = 0; q < 4; q++) c[j][q] = 0.f;

    for (int k0 = 0; k0 < DTXT; k0 += 64) {
        #pragma unroll
        for (int it = 0; it < 4; it++) {
            int fi = tid + it * 256;
            int rr = fi >> 4;
            int kq = fi & 15;
            int gr = r0 + rr;
            float4 v = (gr < N) ? __ldg(((const float4*)(T + (size_t)gr * DTXT + k0)) + kq)
                                : make_float4(0.f, 0.f, 0.f, 0.f);
            *(float4*)(As + rr * ASTR + kq * 4) = v;
        }
        #pragma unroll
        for (int it = 0; it < 4; it++) {
            int fi = tid + it * 256;
            int kk = fi >> 4;
            int cq = fi & 15;
            float4 v = __ldg(((const float4*)(Wt + (size_t)(k0 + kk) * D)) + cq);
            *(float4*)(Bs + kk * BSTR + cq * 4) = v;
        }
        __syncthreads();

        #pragma unroll
        for (int kk = 0; kk < 64; kk += 8) {
            unsigned a0 = __float_as_uint(As[(wr + gid)     * ASTR + kk + tig]);
            unsigned a1 = __float_as_uint(As[(wr + gid + 8) * ASTR + kk + tig]);
            unsigned a2 = __float_as_uint(As[(wr + gid)     * ASTR + kk + tig + 4]);
            unsigned a3 = __float_as_uint(As[(wr + gid + 8) * ASTR + kk + tig + 4]);
            #pragma unroll
            for (int j = 0; j < 4; j++) {
                int cb = wc + j * 8;
                unsigned b0 = __float_as_uint(Bs[(kk + tig)     * BSTR + cb + gid]);
                unsigned b1 = __float_as_uint(Bs[(kk + tig + 4) * BSTR + cb + gid]);
                MMA_TF32(c[j][0], c[j][1], c[j][2], c[j][3], a0, a1, a2, a3, b0, b1);
            }
        }
        __syncthreads();
    }

    int lrA = wr + gid, lrB = lrA + 8;
    int grA = r0 + lrA, grB = r0 + lrB;
    bool okA = grA < N, okB = grB < N;

    float tv[4][4];
    float2 gA[4], gB[4];
    float stA = 0.f, stB = 0.f, sgA = 0.f, sgB = 0.f;
    #pragma unroll
    for (int j = 0; j < 4; j++) {
        int col = wc + j * 8 + 2 * tig;
        float b0 = s_bias[col], b1 = s_bias[col + 1];
        float t0 = c[j][0] + b0, t1 = c[j][1] + b1;
        float t2 = c[j][2] + b0, t3 = c[j][3] + b1;
        tv[j][0] = t0; tv[j][1] = t1; tv[j][2] = t2; tv[j][3] = t3;
        stA += t0 * t0 + t1 * t1;
        stB += t2 * t2 + t3 * t3;
        float2 ga = okA ? *(const float2*)(acc + (size_t)grA * D + col) : make_float2(0.f, 0.f);
        float2 gb = okB ? *(const float2*)(acc + (size_t)grB * D + col) : make_float2(0.f, 0.f);
        gA[j] = ga; gB[j] = gb;
        sgA += ga.x * ga.x + ga.y * ga.y;
        sgB += gb.x * gb.x + gb.y * gb.y;
    }
    #pragma unroll
    for (int m = 1; m < 4; m <<= 1) {
        stA += __shfl_xor_sync(0xffffffffu, stA, m);
        stB += __shfl_xor_sync(0xffffffffu, stB, m);
        sgA += __shfl_xor_sync(0xffffffffu, sgA, m);
        sgB += __shfl_xor_sync(0xffffffffu, sgB, m);
    }
    if (tig == 0) {
        atomicAdd(&s_nt[lrA], stA);
        atomicAdd(&s_nt[lrB], stB);
        atomicAdd(&s_ng[lrA], sgA);
        atomicAdd(&s_ng[lrB], sgB);
    }
    __syncthreads();

    float intA = 1.f / fmaxf(sqrtf(s_nt[lrA]), 1e-12f);
    float intB = 1.f / fmaxf(sqrtf(s_nt[lrB]), 1e-12f);
    float ingA = 1.f / fmaxf(sqrtf(s_ng[lrA]), 1e-12f);
    float ingB = 1.f / fmaxf(sqrtf(s_ng[lrB]), 1e-12f);

    #pragma unroll
    for (int j = 0; j < 4; j++) {
        int col = wc + j * 8 + 2 * tig;
        if (okA)
            *(float2*)(acc + (size_t)grA * D + col) =
                make_float2(0.5f * (gA[j].x * ingA + tv[j][0] * intA),
                            0.5f * (gA[j].y * ingA + tv[j][1] * intA));
        if (okB)
            *(float2*)(acc + (size_t)grB * D + col) =
                make_float2(0.5f * (gB[j].x * ingB + tv[j][2] * intB),
                            0.5f * (gB[j].y * ingB + tv[j][3] * intB));
    }
}

// -------------------- launch --------------------
extern "C" void kernel_launch(void* const* d_in, const int* in_sizes, int n_in,
                              void* d_out, int out_size) {
    const int*   m_row = (const int*)d_in[0];
    const int*   m_col = (const int*)d_in[1];
    const float* m_val = (const float*)d_in[2];
    const int*   a_row = (const int*)d_in[3];
    const int*   a_col = (const int*)d_in[4];
    const float* a_val = (const float*)d_in[5];
    const float* m_txt = (const float*)d_in[6];
    const float* a_txt = (const float*)d_in[7];
    const float* m_emb = (const float*)d_in[8];
    const float* a_emb = (const float*)d_in[9];
    const float* W     = (const float*)d_in[10];
    const float* bias  = (const float*)d_in[11];

    int E_M = in_sizes[0];
    int E_A = in_sizes[3];
    int N_M = in_sizes[8] / D;
    int N_A = in_sizes[9] / D;

    float* out  = (float*)d_out;
    float* outA = out + (size_t)N_M * D;

    ull*   edM;  cudaGetSymbolAddress((void**)&edM,  g_edgesM);
    ull*   edA;  cudaGetSymbolAddress((void**)&edA,  g_edgesA);
    float* bufA; cudaGetSymbolAddress((void**)&bufA, g_bufA);
    float* bufB; cudaGetSymbolAddress((void**)&bufB, g_bufB);
    int*   rpM;  cudaGetSymbolAddress((void**)&rpM,  g_rowptrM);
    int*   rpA;  cudaGetSymbolAddress((void**)&rpA,  g_rowptrA);
    int*   cnt;  cudaGetSymbolAddress((void**)&cnt,  g_cnt);
    float* wt;   cudaGetSymbolAddress((void**)&wt,   g_wt);

    int* cntM = cnt;
    int* cntA = cnt + MAXN;

    const int TB = 256;
    int maxE = (E_M > E_A) ? E_M : E_A;
    int eg4  = (maxE + 4 * TB - 1) / (4 * TB);
    int sgM  = (N_M * 16 + TB - 1) / TB;
    int sgA  = (N_A * 16 + TB - 1) / TB;

    // prep
    k_prepw<<<(DTXT * D + TB - 1) / TB, TB>>>(W, wt, DTXT * D);
    cudaMemsetAsync(cnt, 0, 2 * (size_t)MAXN * sizeof(int));

    // CSR builds (both graphs per launch via blockIdx.y)
    dim3 eg(eg4, 2);
    k_hist4<<<eg, TB>>>(m_row, a_row, cntM, cntA, E_M, E_A);
    k_scan2<<<2, 1024>>>(cntM, rpM, cntA, rpA, N_M);   // N_M == N_A
    k_scatter4<<<eg, TB>>>(m_row, m_col, m_val, a_row, a_col, a_val,
                           cntM, cntA, edM, edA, E_M, E_A);

    // graph M propagation
    k_spmm_csr<<<sgM, TB>>>(edM, rpM, m_emb, m_emb, bufA,      out, N_M);
    k_spmm_csr<<<sgM, TB>>>(edM, rpM, bufA,  out,   bufB,      out, N_M);
    k_spmm_csr<<<sgM, TB>>>(edM, rpM, bufB,  out,   (float*)0, out, N_M);

    // graph A propagation
    k_spmm_csr<<<sgA, TB>>>(edA, rpA, a_emb, a_emb, bufA,      outA, N_A);
    k_spmm_csr<<<sgA, TB>>>(edA, rpA, bufA,  outA,  bufB,      outA, N_A);
    k_spmm_csr<<<sgA, TB>>>(edA, rpA, bufB,  outA,  (float*)0, outA, N_A);

    // text GEMM + norms + combine
    int maxN = (N_M > N_A) ? N_M : N_A;
    dim3 grid((maxN + 63) / 64, 2);
    k_textfinal<<<grid, 256>>>(m_txt, a_txt, wt, bias, out, N_M, N_A);
}